// round 6
// baseline (speedup 1.0000x reference)
#include <cuda_runtime.h>
#include <math.h>

#define Bsz 64
#define Tsz 2048
#define Dsz 256
#define Hsz 512
#define Gsz 2048
#define NB  128

typedef unsigned long long u64;

// ---- packed fp32x2 helpers (Blackwell FFMA2/FADD2, PTX-only) ----
__device__ __forceinline__ u64 ffma2(u64 a, u64 b, u64 c) {
    u64 d;
    asm("fma.rn.f32x2 %0, %1, %2, %3;" : "=l"(d) : "l"(a), "l"(b), "l"(c));
    return d;
}
__device__ __forceinline__ u64 fadd2(u64 a, u64 b) {
    u64 d;
    asm("add.rn.f32x2 %0, %1, %2;" : "=l"(d) : "l"(a), "l"(b));
    return d;
}
__device__ __forceinline__ u64 dup2(float x) {
    u64 d;
    asm("mov.b64 %0, {%1, %1};" : "=l"(d) : "r"(__float_as_uint(x)));
    return d;
}
__device__ __forceinline__ float lo2(u64 d) { return __int_as_float((int)(unsigned)(d & 0xffffffffu)); }
__device__ __forceinline__ float hi2(u64 d) { return __int_as_float((int)(unsigned)(d >> 32)); }

// Scratch (device globals)
__device__ float g_xw[(size_t)Tsz * Gsz * Bsz];    // [t][col][b]  1 GiB
__device__ float g_Up[64 * Hsz * 32];              // [cg][k][c]   4 MB
__device__ float g_h[2 * Hsz * Bsz];               // [parity][j][b]
__device__ int   g_flagv[2][64];                   // dataflow flags: steps completed

__global__ void reset_bar_k() {
    int i = threadIdx.x;
    if (i < 64) { g_flagv[0][i] = 0; g_flagv[1][i] = 0; }
}

// g_Up[cg][k][c] = U[k][gate*512 + cg*8 + jj], c = gate*8 + jj  (32 cols per cg)
__global__ void pack_U_k(const float* __restrict__ U) {
    int idx = blockIdx.x * blockDim.x + threadIdx.x;   // 2^20 total
    int c  = idx & 31;
    int k  = (idx >> 5) & (Hsz - 1);
    int cg = idx >> 14;
    g_Up[idx] = U[k * Gsz + (c >> 3) * Hsz + cg * 8 + (c & 7)];
}

// xW GEMM with FFMA2: C[b][col] = sum_k x[b,t,k]*W[k,col] + bias[col] -> [t][col][b]
__global__ __launch_bounds__(256, 2) void gemm_xw_k(const float* __restrict__ x,
                                                    const float* __restrict__ W,
                                                    const float* __restrict__ bias) {
    const int t   = blockIdx.y;
    const int cb  = blockIdx.x;
    const int tid = threadIdx.x;
    __shared__ float As[32 * 68];
    __shared__ float Bs[32 * 132];
    const int b0 = (tid & 15) * 4;
    const int c0 = (tid >> 4) * 8;

    u64 acc[4][4];
    {
        ulonglong2 bb0 = *(const ulonglong2*)(bias + cb * 128 + c0);
        ulonglong2 bb1 = *(const ulonglong2*)(bias + cb * 128 + c0 + 4);
#pragma unroll
        for (int i = 0; i < 4; ++i) {
            acc[i][0] = bb0.x; acc[i][1] = bb0.y;
            acc[i][2] = bb1.x; acc[i][3] = bb1.y;
        }
    }
    const int arow = tid >> 3;
    const int af4  = tid & 7;
    const int wk   = tid >> 3;
    const int wc   = (tid & 7) * 16;

    for (int k0 = 0; k0 < Dsz; k0 += 32) {
#pragma unroll
        for (int pass = 0; pass < 2; ++pass) {
            int b = arow + pass * 32;
            float4 v = *(const float4*)(x + ((size_t)b * Tsz + t) * Dsz + k0 + af4 * 4);
            As[(af4 * 4 + 0) * 68 + b] = v.x;
            As[(af4 * 4 + 1) * 68 + b] = v.y;
            As[(af4 * 4 + 2) * 68 + b] = v.z;
            As[(af4 * 4 + 3) * 68 + b] = v.w;
        }
        const float* wp = W + (size_t)(k0 + wk) * Gsz + cb * 128 + wc;
        float4 w0 = ((const float4*)wp)[0];
        float4 w1 = ((const float4*)wp)[1];
        float4 w2 = ((const float4*)wp)[2];
        float4 w3 = ((const float4*)wp)[3];
        *(float4*)&Bs[wk * 132 + wc + 0]  = w0;
        *(float4*)&Bs[wk * 132 + wc + 4]  = w1;
        *(float4*)&Bs[wk * 132 + wc + 8]  = w2;
        *(float4*)&Bs[wk * 132 + wc + 12] = w3;
        __syncthreads();
#pragma unroll
        for (int kk = 0; kk < 32; ++kk) {
            float4 a = *(const float4*)&As[kk * 68 + b0];
            ulonglong2 u01 = *(const ulonglong2*)&Bs[kk * 132 + c0];
            ulonglong2 u23 = *(const ulonglong2*)&Bs[kk * 132 + c0 + 4];
            u64 a0 = dup2(a.x), a1 = dup2(a.y), a2 = dup2(a.z), a3 = dup2(a.w);
            acc[0][0] = ffma2(a0, u01.x, acc[0][0]);
            acc[1][0] = ffma2(a1, u01.x, acc[1][0]);
            acc[2][0] = ffma2(a2, u01.x, acc[2][0]);
            acc[3][0] = ffma2(a3, u01.x, acc[3][0]);
            acc[0][1] = ffma2(a0, u01.y, acc[0][1]);
            acc[1][1] = ffma2(a1, u01.y, acc[1][1]);
            acc[2][1] = ffma2(a2, u01.y, acc[2][1]);
            acc[3][1] = ffma2(a3, u01.y, acc[3][1]);
            acc[0][2] = ffma2(a0, u23.x, acc[0][2]);
            acc[1][2] = ffma2(a1, u23.x, acc[1][2]);
            acc[2][2] = ffma2(a2, u23.x, acc[2][2]);
            acc[3][2] = ffma2(a3, u23.x, acc[3][2]);
            acc[0][3] = ffma2(a0, u23.y, acc[0][3]);
            acc[1][3] = ffma2(a1, u23.y, acc[1][3]);
            acc[2][3] = ffma2(a2, u23.y, acc[2][3]);
            acc[3][3] = ffma2(a3, u23.y, acc[3][3]);
        }
        __syncthreads();
    }
#pragma unroll
    for (int jp = 0; jp < 4; ++jp) {
        float4 lo = make_float4(lo2(acc[0][jp]), lo2(acc[1][jp]), lo2(acc[2][jp]), lo2(acc[3][jp]));
        float4 hi = make_float4(hi2(acc[0][jp]), hi2(acc[1][jp]), hi2(acc[2][jp]), hi2(acc[3][jp]));
        size_t base = (size_t)t * Gsz + cb * 128;
        *(float4*)&g_xw[(base + c0 + 2 * jp) * 64 + b0]     = lo;
        *(float4*)&g_xw[(base + c0 + 2 * jp + 1) * 64 + b0] = hi;
    }
}

// Persistent recurrence — per-warp dataflow, no global barrier.
// 128 CTAs = (b-half bh) x (64 col-groups cg: 8 hidden units = 32 gate cols).
// 8 warps; warp w owns k in [64w, 64w+64). Before each step's compute, warp w
// spins on flags of the 8 producer CTAs covering its k-rows (flag = #steps
// completed; 2-buffer h is safe because flag(t) implies that CTA finished
// READING buffer (t-1)&1). Warp stages its own 8KB h slice (LDG.cg -> STS,
// no cross-warp sync), computes conflict-free 8b x 4c tiles with FFMA2.
// 3 __syncthreads per step (partials, reduce, pre-flag).
// Smem: Us[512][32] + hs[8][64][32] + part[8][32][32] + red[32][36].
#define REC_SMEM_FLOATS (16384 + 16384 + 8192 + 32 * 36)

__global__ __launch_bounds__(256, 1) void lstm_rec_k(float* __restrict__ out) {
    extern __shared__ float sm[];
    float* Us   = sm;            // [512][32]
    float* hs   = sm + 16384;    // [w][64][32]
    float* part = sm + 32768;    // [w][c][b]
    float* red  = sm + 40960;    // [32][36]

    const int n   = blockIdx.x;
    const int tid = threadIdx.x;
    const int bh  = n & 1;
    const int cg  = n >> 1;
    const int w   = tid >> 5;
    const int L   = tid & 31;
    const int b0  = (L & 3) * 8;
    const int c0  = (L >> 2) * 4;
    const int ub  = tid & 31;          // update role: batch within half
    const int ujj = tid >> 5;          // update role: hidden-within-cg 0..7
    const int jbase = cg * 8;

    // resident U slice [512][32]
    {
        const float4* Usrc = (const float4*)(g_Up + (size_t)cg * 16384);
        float4* Udst = (float4*)Us;
        for (int i = tid; i < 4096; i += 256) Udst[i] = Usrc[i];
    }

    // zero h parity 0 (this CTA's slice), publish flag = 1
    g_h[(jbase + ujj) * 64 + bh * 32 + ub] = 0.0f;
    float creg = 0.0f, hreg = 0.0f;
    __syncthreads();
    if (tid == 0) {
        __threadfence();
        *((volatile int*)&g_flagv[bh][cg]) = 1;
    }

    float* hw = hs + w * 2048;         // this warp's staging area

    for (int step = 0; step < Tsz; ++step) {
        const int p = step & 1;
        const float* hq = g_h + p * (Hsz * Bsz) + bh * 32;   // row stride 64

        // xW loads in flight during the spin
        const size_t xbase = (size_t)step * Gsz;
        float xg0 = __ldcs(&g_xw[(xbase + 0 * Hsz + jbase + ujj) * 64 + bh * 32 + ub]);
        float xg1 = __ldcs(&g_xw[(xbase + 1 * Hsz + jbase + ujj) * 64 + bh * 32 + ub]);
        float xg2 = __ldcs(&g_xw[(xbase + 2 * Hsz + jbase + ujj) * 64 + bh * 32 + ub]);
        float xg3 = __ldcs(&g_xw[(xbase + 3 * Hsz + jbase + ujj) * 64 + bh * 32 + ub]);

        // wait for the 8 producers of this warp's k-rows
        {
            const int need = step + 1;
            const volatile int* fl = (const volatile int*)&g_flagv[bh][8 * w];
            for (;;) {
                int v = (L < 8) ? fl[L] : 0x7fffffff;
                if (__all_sync(0xffffffffu, v >= need)) break;
                __nanosleep(32);
            }
        }
        __threadfence();

        // stage this warp's k-slice: rows [64w, 64w+64) x 32 floats (8KB)
        {
            float4 pv[16];
#pragma unroll
            for (int m = 0; m < 16; ++m) {
                int idx = L + 32 * m;          // 512 float4 slots
                int r = idx >> 3, q = idx & 7;
                pv[m] = __ldcg((const float4*)(hq + (w * 64 + r) * 64) + q);
            }
#pragma unroll
            for (int m = 0; m < 16; ++m) {
                int idx = L + 32 * m;
                int r = idx >> 3, q = idx & 7;
                *(float4*)&hw[r * 32 + q * 4] = pv[m];
            }
        }

        // compute: k in [64w, 64w+64); acc[j*4+i]: col c0+j, b-pair i
        u64 acc[16];
#pragma unroll
        for (int j = 0; j < 16; ++j) acc[j] = 0ull;
#pragma unroll 16
        for (int i = 0; i < 64; ++i) {
            ulonglong2 hA = *(const ulonglong2*)&hw[i * 32 + b0];
            ulonglong2 hB = *(const ulonglong2*)&hw[i * 32 + b0 + 4];
            float4 uq = *(const float4*)&Us[(w * 64 + i) * 32 + c0];
            u64 u0 = dup2(uq.x), u1 = dup2(uq.y), u2 = dup2(uq.z), u3 = dup2(uq.w);
            acc[0]  = ffma2(hA.x, u0, acc[0]);
            acc[1]  = ffma2(hA.y, u0, acc[1]);
            acc[2]  = ffma2(hB.x, u0, acc[2]);
            acc[3]  = ffma2(hB.y, u0, acc[3]);
            acc[4]  = ffma2(hA.x, u1, acc[4]);
            acc[5]  = ffma2(hA.y, u1, acc[5]);
            acc[6]  = ffma2(hB.x, u1, acc[6]);
            acc[7]  = ffma2(hB.y, u1, acc[7]);
            acc[8]  = ffma2(hA.x, u2, acc[8]);
            acc[9]  = ffma2(hA.y, u2, acc[9]);
            acc[10] = ffma2(hB.x, u2, acc[10]);
            acc[11] = ffma2(hB.y, u2, acc[11]);
            acc[12] = ffma2(hA.x, u3, acc[12]);
            acc[13] = ffma2(hA.y, u3, acc[13]);
            acc[14] = ffma2(hB.x, u3, acc[14]);
            acc[15] = ffma2(hB.y, u3, acc[15]);
        }

        // per-warp partial tile [32c][32b] (own region, no pre-sync needed)
#pragma unroll
        for (int j = 0; j < 4; ++j) {
            float* pp = part + w * 1024 + (c0 + j) * 32 + b0;
            *(ulonglong2*)pp       = make_ulonglong2(acc[4 * j + 0], acc[4 * j + 1]);
            *(ulonglong2*)(pp + 4) = make_ulonglong2(acc[4 * j + 2], acc[4 * j + 3]);
        }
        __syncthreads();

        // reduce over 8 warps: thread -> col c=tid>>3, b-quad q=tid&7
        {
            const int rc = tid >> 3, rq = (tid & 7) * 4;
            ulonglong2 s = *(const ulonglong2*)&part[rc * 32 + rq];
#pragma unroll
            for (int ww = 1; ww < 8; ++ww) {
                ulonglong2 v = *(const ulonglong2*)&part[ww * 1024 + rc * 32 + rq];
                s.x = fadd2(s.x, v.x);
                s.y = fadd2(s.y, v.y);
            }
            *(ulonglong2*)&red[rc * 36 + rq] = s;
        }
        __syncthreads();

        // elementwise update: thread owns (b = ub, j = jbase + ujj)
        float v0 = red[(0 * 8 + ujj) * 36 + ub] + xg0;
        float v1 = red[(1 * 8 + ujj) * 36 + ub] + xg1;
        float v2 = red[(2 * 8 + ujj) * 36 + ub] + xg2;
        float v3 = red[(3 * 8 + ujj) * 36 + ub] + xg3;
        float ig = 1.0f / (1.0f + __expf(-v0));
        float fg = 1.0f / (1.0f + __expf(-v1));
        float gg = tanhf(v2);
        float og = 1.0f / (1.0f + __expf(-v3));
        creg = fg * creg + ig * gg;
        hreg = og * tanhf(creg);
        g_h[(p ^ 1) * (Hsz * Bsz) + (jbase + ujj) * 64 + bh * 32 + ub] = hreg;

        __syncthreads();               // all h writes of this CTA done
        if (tid == 0) {
            __threadfence();
            *((volatile int*)&g_flagv[bh][cg]) = step + 2;
        }
    }

    out[(bh * 32 + ub) * Hsz + jbase + ujj] = hreg;
    out[Bsz * Hsz + (bh * 32 + ub) * Hsz + jbase + ujj] = creg;
}

extern "C" void kernel_launch(void* const* d_in, const int* in_sizes, int n_in,
                              void* d_out, int out_size) {
    const float* x    = (const float*)d_in[0];
    const float* W    = (const float*)d_in[1];
    const float* U    = (const float*)d_in[2];
    const float* bias = (const float*)d_in[3];
    float* out = (float*)d_out;
    (void)in_sizes; (void)n_in; (void)out_size;

    static int smem_set = 0;
    if (!smem_set) {
        cudaFuncSetAttribute(lstm_rec_k, cudaFuncAttributeMaxDynamicSharedMemorySize,
                             REC_SMEM_FLOATS * 4);
        smem_set = 1;
    }

    pack_U_k<<<2048, 512>>>(U);
    dim3 g(16, Tsz);
    gemm_xw_k<<<g, 256>>>(x, W, bias);
    reset_bar_k<<<1, 64>>>();
    lstm_rec_k<<<NB, 256, REC_SMEM_FLOATS * 4>>>(out);
}

// round 7
// speedup vs baseline: 1.3577x; 1.3577x over previous
#include <cuda_runtime.h>
#include <math.h>

#define Bsz 64
#define Tsz 2048
#define Dsz 256
#define Hsz 512
#define Gsz 2048
#define NB  128

typedef unsigned long long u64;

// ---- packed fp32x2 helpers (Blackwell FFMA2/FADD2, PTX-only) ----
__device__ __forceinline__ u64 ffma2(u64 a, u64 b, u64 c) {
    u64 d;
    asm("fma.rn.f32x2 %0, %1, %2, %3;" : "=l"(d) : "l"(a), "l"(b), "l"(c));
    return d;
}
__device__ __forceinline__ u64 fadd2(u64 a, u64 b) {
    u64 d;
    asm("add.rn.f32x2 %0, %1, %2;" : "=l"(d) : "l"(a), "l"(b));
    return d;
}
__device__ __forceinline__ u64 dup2(float x) {
    u64 d;
    asm("mov.b64 %0, {%1, %1};" : "=l"(d) : "r"(__float_as_uint(x)));
    return d;
}
__device__ __forceinline__ float lo2(u64 d) { return __int_as_float((int)(unsigned)(d & 0xffffffffu)); }
__device__ __forceinline__ float hi2(u64 d) { return __int_as_float((int)(unsigned)(d >> 32)); }

// Scratch (device globals)
__device__ float g_xw[(size_t)Tsz * Gsz * Bsz];    // [t][col][b]  1 GiB
__device__ float g_Up[64 * Hsz * 32];              // [cg][k][c]   4 MB
__device__ float g_h[2 * Hsz * Bsz];               // [parity][j][b]
__device__ unsigned g_cnt;                         // single arrival counter

__global__ void reset_bar_k() { g_cnt = 0u; }

// g_Up[cg][k][c] = U[k][gate*512 + cg*8 + jj], c = gate*8 + jj  (32 cols per cg)
__global__ void pack_U_k(const float* __restrict__ U) {
    int idx = blockIdx.x * blockDim.x + threadIdx.x;   // 2^20 total
    int c  = idx & 31;
    int k  = (idx >> 5) & (Hsz - 1);
    int cg = idx >> 14;
    g_Up[idx] = U[k * Gsz + (c >> 3) * Hsz + cg * 8 + (c & 7)];
}

// xW GEMM with FFMA2: C[b][col] = sum_k x[b,t,k]*W[k,col] + bias[col] -> [t][col][b]
__global__ __launch_bounds__(256, 2) void gemm_xw_k(const float* __restrict__ x,
                                                    const float* __restrict__ W,
                                                    const float* __restrict__ bias) {
    const int t   = blockIdx.y;
    const int cb  = blockIdx.x;
    const int tid = threadIdx.x;
    __shared__ float As[32 * 68];
    __shared__ float Bs[32 * 132];
    const int b0 = (tid & 15) * 4;
    const int c0 = (tid >> 4) * 8;

    u64 acc[4][4];
    {
        ulonglong2 bb0 = *(const ulonglong2*)(bias + cb * 128 + c0);
        ulonglong2 bb1 = *(const ulonglong2*)(bias + cb * 128 + c0 + 4);
#pragma unroll
        for (int i = 0; i < 4; ++i) {
            acc[i][0] = bb0.x; acc[i][1] = bb0.y;
            acc[i][2] = bb1.x; acc[i][3] = bb1.y;
        }
    }
    const int arow = tid >> 3;
    const int af4  = tid & 7;
    const int wk   = tid >> 3;
    const int wc   = (tid & 7) * 16;

    for (int k0 = 0; k0 < Dsz; k0 += 32) {
#pragma unroll
        for (int pass = 0; pass < 2; ++pass) {
            int b = arow + pass * 32;
            float4 v = *(const float4*)(x + ((size_t)b * Tsz + t) * Dsz + k0 + af4 * 4);
            As[(af4 * 4 + 0) * 68 + b] = v.x;
            As[(af4 * 4 + 1) * 68 + b] = v.y;
            As[(af4 * 4 + 2) * 68 + b] = v.z;
            As[(af4 * 4 + 3) * 68 + b] = v.w;
        }
        const float* wp = W + (size_t)(k0 + wk) * Gsz + cb * 128 + wc;
        float4 w0 = ((const float4*)wp)[0];
        float4 w1 = ((const float4*)wp)[1];
        float4 w2 = ((const float4*)wp)[2];
        float4 w3 = ((const float4*)wp)[3];
        *(float4*)&Bs[wk * 132 + wc + 0]  = w0;
        *(float4*)&Bs[wk * 132 + wc + 4]  = w1;
        *(float4*)&Bs[wk * 132 + wc + 8]  = w2;
        *(float4*)&Bs[wk * 132 + wc + 12] = w3;
        __syncthreads();
#pragma unroll
        for (int kk = 0; kk < 32; ++kk) {
            float4 a = *(const float4*)&As[kk * 68 + b0];
            ulonglong2 u01 = *(const ulonglong2*)&Bs[kk * 132 + c0];
            ulonglong2 u23 = *(const ulonglong2*)&Bs[kk * 132 + c0 + 4];
            u64 a0 = dup2(a.x), a1 = dup2(a.y), a2 = dup2(a.z), a3 = dup2(a.w);
            acc[0][0] = ffma2(a0, u01.x, acc[0][0]);
            acc[1][0] = ffma2(a1, u01.x, acc[1][0]);
            acc[2][0] = ffma2(a2, u01.x, acc[2][0]);
            acc[3][0] = ffma2(a3, u01.x, acc[3][0]);
            acc[0][1] = ffma2(a0, u01.y, acc[0][1]);
            acc[1][1] = ffma2(a1, u01.y, acc[1][1]);
            acc[2][1] = ffma2(a2, u01.y, acc[2][1]);
            acc[3][1] = ffma2(a3, u01.y, acc[3][1]);
            acc[0][2] = ffma2(a0, u23.x, acc[0][2]);
            acc[1][2] = ffma2(a1, u23.x, acc[1][2]);
            acc[2][2] = ffma2(a2, u23.x, acc[2][2]);
            acc[3][2] = ffma2(a3, u23.x, acc[3][2]);
            acc[0][3] = ffma2(a0, u23.y, acc[0][3]);
            acc[1][3] = ffma2(a1, u23.y, acc[1][3]);
            acc[2][3] = ffma2(a2, u23.y, acc[2][3]);
            acc[3][3] = ffma2(a3, u23.y, acc[3][3]);
        }
        __syncthreads();
    }
#pragma unroll
    for (int jp = 0; jp < 4; ++jp) {
        float4 lo = make_float4(lo2(acc[0][jp]), lo2(acc[1][jp]), lo2(acc[2][jp]), lo2(acc[3][jp]));
        float4 hi = make_float4(hi2(acc[0][jp]), hi2(acc[1][jp]), hi2(acc[2][jp]), hi2(acc[3][jp]));
        size_t base = (size_t)t * Gsz + cb * 128;
        *(float4*)&g_xw[(base + c0 + 2 * jp) * 64 + b0]     = lo;
        *(float4*)&g_xw[(base + c0 + 2 * jp + 1) * 64 + b0] = hi;
    }
}

// ---- chip barrier: release-REDG arrive + acquire-poll wait (no MEMBAR) ----
__device__ __forceinline__ void garrive_all() {
    __syncthreads();                 // all threads' h stores program-ordered before tid0's RED
    if (threadIdx.x == 0) {
        asm volatile("red.release.gpu.add.u32 [%0], %1;" :: "l"(&g_cnt), "r"(1u) : "memory");
    }
}
__device__ __forceinline__ void gwait_all(unsigned target) {
    if (threadIdx.x == 0) {
        unsigned v;
        do {
            asm volatile("ld.acquire.gpu.u32 %0, [%1];" : "=r"(v) : "l"(&g_cnt) : "memory");
        } while (v < target);
    }
    __syncthreads();                 // broadcast acquire to whole CTA
}

// Persistent recurrence — per-warp double-buffered self-staging + acq/rel barrier.
// 128 CTAs = (b-half bh) x (64 col-groups cg: 8 hidden units = 32 gate cols).
// 8 warps; warp w owns k in [64w, 64w+64), staged warp-locally in two 32-row
// halves (LDG-B latency hidden under compute-A). Tile 8b x 4c, 16 FFMA2/k.
// 4 __syncthreads per step. Smem: Us[512][32] + hs[8][64][32] + part + red.
#define REC_SMEM_FLOATS (16384 + 16384 + 8192 + 32 * 36)

__global__ __launch_bounds__(256, 1) void lstm_rec_k(float* __restrict__ out) {
    extern __shared__ float sm[];
    float* Us   = sm;            // [512][32]
    float* hs   = sm + 16384;    // [w][64][32]
    float* part = sm + 32768;    // [w][c][b]
    float* red  = sm + 40960;    // [32][36]

    const int n   = blockIdx.x;
    const int tid = threadIdx.x;
    const int bh  = n & 1;
    const int cg  = n >> 1;
    const int w   = tid >> 5;
    const int L   = tid & 31;
    const int b0  = (L & 3) * 8;
    const int c0  = (L >> 2) * 4;
    const int ub  = tid & 31;          // update role: batch within half
    const int ujj = tid >> 5;          // update role: hidden-within-cg 0..7
    const int jbase = cg * 8;

    // resident U slice [512][32]
    {
        const float4* Usrc = (const float4*)(g_Up + (size_t)cg * 16384);
        float4* Udst = (float4*)Us;
        for (int i = tid; i < 4096; i += 256) Udst[i] = Usrc[i];
    }

    // zero h parity 0 (this CTA's slice)
    g_h[(jbase + ujj) * 64 + bh * 32 + ub] = 0.0f;
    float creg = 0.0f, hreg = 0.0f;

    unsigned target = NB;
    garrive_all();

    float* hw = hs + w * 2048;         // this warp's staging area [64][32]

    for (int step = 0; step < Tsz; ++step) {
        const int p = step & 1;
        const float* hq = g_h + p * (Hsz * Bsz) + bh * 32;   // row stride 64

        // xW loads in flight across the barrier wait
        const size_t xbase = (size_t)step * Gsz;
        float xg0 = __ldcs(&g_xw[(xbase + 0 * Hsz + jbase + ujj) * 64 + bh * 32 + ub]);
        float xg1 = __ldcs(&g_xw[(xbase + 1 * Hsz + jbase + ujj) * 64 + bh * 32 + ub]);
        float xg2 = __ldcs(&g_xw[(xbase + 2 * Hsz + jbase + ujj) * 64 + bh * 32 + ub]);
        float xg3 = __ldcs(&g_xw[(xbase + 3 * Hsz + jbase + ujj) * 64 + bh * 32 + ub]);

        gwait_all(target);
        target += NB;

        u64 acc[16];
#pragma unroll
        for (int j = 0; j < 16; ++j) acc[j] = 0ull;

        // ---- stage half A (rows [64w, 64w+32)) ----
        float4 pv[8];
#pragma unroll
        for (int m = 0; m < 8; ++m) {
            int idx = L + 32 * m; int r = idx >> 3, q = idx & 7;
            pv[m] = __ldcg((const float4*)(hq + (w * 64 + r) * 64) + q);
        }
#pragma unroll
        for (int m = 0; m < 8; ++m) {
            int idx = L + 32 * m; int r = idx >> 3, q = idx & 7;
            *(float4*)&hw[r * 32 + q * 4] = pv[m];
        }
        // issue LDG for half B (latency hides under compute A)
        float4 pw[8];
#pragma unroll
        for (int m = 0; m < 8; ++m) {
            int idx = L + 32 * m; int r = 32 + (idx >> 3), q = idx & 7;
            pw[m] = __ldcg((const float4*)(hq + (w * 64 + r) * 64) + q);
        }
        __syncwarp();

        // ---- compute half A ----
#pragma unroll 16
        for (int i = 0; i < 32; ++i) {
            ulonglong2 hA = *(const ulonglong2*)&hw[i * 32 + b0];
            ulonglong2 hB = *(const ulonglong2*)&hw[i * 32 + b0 + 4];
            float4 uq = *(const float4*)&Us[(w * 64 + i) * 32 + c0];
            u64 u0 = dup2(uq.x), u1 = dup2(uq.y), u2 = dup2(uq.z), u3 = dup2(uq.w);
            acc[0]  = ffma2(hA.x, u0, acc[0]);
            acc[1]  = ffma2(hA.y, u0, acc[1]);
            acc[2]  = ffma2(hB.x, u0, acc[2]);
            acc[3]  = ffma2(hB.y, u0, acc[3]);
            acc[4]  = ffma2(hA.x, u1, acc[4]);
            acc[5]  = ffma2(hA.y, u1, acc[5]);
            acc[6]  = ffma2(hB.x, u1, acc[6]);
            acc[7]  = ffma2(hB.y, u1, acc[7]);
            acc[8]  = ffma2(hA.x, u2, acc[8]);
            acc[9]  = ffma2(hA.y, u2, acc[9]);
            acc[10] = ffma2(hB.x, u2, acc[10]);
            acc[11] = ffma2(hB.y, u2, acc[11]);
            acc[12] = ffma2(hA.x, u3, acc[12]);
            acc[13] = ffma2(hA.y, u3, acc[13]);
            acc[14] = ffma2(hB.x, u3, acc[14]);
            acc[15] = ffma2(hB.y, u3, acc[15]);
        }

        // ---- stage half B ----
#pragma unroll
        for (int m = 0; m < 8; ++m) {
            int idx = L + 32 * m; int r = 32 + (idx >> 3), q = idx & 7;
            *(float4*)&hw[r * 32 + q * 4] = pw[m];
        }
        __syncwarp();

        // ---- compute half B ----
#pragma unroll 16
        for (int i = 32; i < 64; ++i) {
            ulonglong2 hA = *(const ulonglong2*)&hw[i * 32 + b0];
            ulonglong2 hB = *(const ulonglong2*)&hw[i * 32 + b0 + 4];
            float4 uq = *(const float4*)&Us[(w * 64 + i) * 32 + c0];
            u64 u0 = dup2(uq.x), u1 = dup2(uq.y), u2 = dup2(uq.z), u3 = dup2(uq.w);
            acc[0]  = ffma2(hA.x, u0, acc[0]);
            acc[1]  = ffma2(hA.y, u0, acc[1]);
            acc[2]  = ffma2(hB.x, u0, acc[2]);
            acc[3]  = ffma2(hB.y, u0, acc[3]);
            acc[4]  = ffma2(hA.x, u1, acc[4]);
            acc[5]  = ffma2(hA.y, u1, acc[5]);
            acc[6]  = ffma2(hB.x, u1, acc[6]);
            acc[7]  = ffma2(hB.y, u1, acc[7]);
            acc[8]  = ffma2(hA.x, u2, acc[8]);
            acc[9]  = ffma2(hA.y, u2, acc[9]);
            acc[10] = ffma2(hB.x, u2, acc[10]);
            acc[11] = ffma2(hB.y, u2, acc[11]);
            acc[12] = ffma2(hA.x, u3, acc[12]);
            acc[13] = ffma2(hA.y, u3, acc[13]);
            acc[14] = ffma2(hB.x, u3, acc[14]);
            acc[15] = ffma2(hB.y, u3, acc[15]);
        }

        // per-warp partial tile [32c][32b] (own region)
#pragma unroll
        for (int j = 0; j < 4; ++j) {
            float* pp = part + w * 1024 + (c0 + j) * 32 + b0;
            *(ulonglong2*)pp       = make_ulonglong2(acc[4 * j + 0], acc[4 * j + 1]);
            *(ulonglong2*)(pp + 4) = make_ulonglong2(acc[4 * j + 2], acc[4 * j + 3]);
        }
        __syncthreads();

        // reduce over 8 warps: thread -> col c=tid>>3, b-quad q=tid&7
        {
            const int rc = tid >> 3, rq = (tid & 7) * 4;
            ulonglong2 s = *(const ulonglong2*)&part[rc * 32 + rq];
#pragma unroll
            for (int ww = 1; ww < 8; ++ww) {
                ulonglong2 v = *(const ulonglong2*)&part[ww * 1024 + rc * 32 + rq];
                s.x = fadd2(s.x, v.x);
                s.y = fadd2(s.y, v.y);
            }
            *(ulonglong2*)&red[rc * 36 + rq] = s;
        }
        __syncthreads();

        // elementwise update: thread owns (b = ub, j = jbase + ujj)
        float v0 = red[(0 * 8 + ujj) * 36 + ub] + xg0;
        float v1 = red[(1 * 8 + ujj) * 36 + ub] + xg1;
        float v2 = red[(2 * 8 + ujj) * 36 + ub] + xg2;
        float v3 = red[(3 * 8 + ujj) * 36 + ub] + xg3;
        float ig = 1.0f / (1.0f + __expf(-v0));
        float fg = 1.0f / (1.0f + __expf(-v1));
        float gg = tanhf(v2);
        float og = 1.0f / (1.0f + __expf(-v3));
        creg = fg * creg + ig * gg;
        hreg = og * tanhf(creg);
        __stcg(&g_h[(p ^ 1) * (Hsz * Bsz) + (jbase + ujj) * 64 + bh * 32 + ub], hreg);

        garrive_all();
    }

    out[(bh * 32 + ub) * Hsz + jbase + ujj] = hreg;
    out[Bsz * Hsz + (bh * 32 + ub) * Hsz + jbase + ujj] = creg;
}

extern "C" void kernel_launch(void* const* d_in, const int* in_sizes, int n_in,
                              void* d_out, int out_size) {
    const float* x    = (const float*)d_in[0];
    const float* W    = (const float*)d_in[1];
    const float* U    = (const float*)d_in[2];
    const float* bias = (const float*)d_in[3];
    float* out = (float*)d_out;
    (void)in_sizes; (void)n_in; (void)out_size;

    static int smem_set = 0;
    if (!smem_set) {
        cudaFuncSetAttribute(lstm_rec_k, cudaFuncAttributeMaxDynamicSharedMemorySize,
                             REC_SMEM_FLOATS * 4);
        smem_set = 1;
    }

    pack_U_k<<<2048, 512>>>(U);
    dim3 g(16, Tsz);
    gemm_xw_k<<<g, 256>>>(x, W, bias);
    reset_bar_k<<<1, 1>>>();
    lstm_rec_k<<<NB, 256, REC_SMEM_FLOATS * 4>>>(out);
}